// round 8
// baseline (speedup 1.0000x reference)
#include <cuda_runtime.h>
#include <math_constants.h>

// ---------------------------------------------------------------------------
// Fused RegionSelector: one block per batch (128 blocks x 1024 threads).
//
// Per batch (512x512 fp32 map):
//   1. 4x4 grid-cell sums (each 128x128). Mean's /16384 scale skipped:
//      uniform positive factor, argmax-invariant.
//   2. Four overlapping 3x3 window sums over the 4x4 cell grid.
//   3. First-occurrence argmax (== jax.lax.top_k tie-break), emit (row, col).
//
// Output written as FLOAT32 (harness __output__ dtype): values 0.0/1.0.
//
// Thread mapping (verified numerically in round 7 diagnostics):
//   cell = t>>6 (64 threads/cell), u = t&63, c4 = u&31 (float4 col),
//   r0 = u>>5 (row parity), rows r0+2i. Each warp = one (cell, parity):
//   lanes read 32 consecutive float4 = 512 contiguous bytes, fully coalesced,
//   8-deep unrolled independent loads (MLP~8).
// ---------------------------------------------------------------------------
__global__ __launch_bounds__(1024) void region_selector_kernel(
    const float* __restrict__ x, float* __restrict__ out)
{
    const int b = blockIdx.x;            // batch 0..127
    const int t = threadIdx.x;           // 0..1023

    const int cell = t >> 6;             // 0..15
    const int u    = t & 63;
    const int gr   = cell >> 2;
    const int gc   = cell & 3;
    const int c4   = u & 31;
    const int r0   = u >> 5;

    const float4* __restrict__ p =
        reinterpret_cast<const float4*>(x) + (size_t)b * 65536;
    const int cellbase = gr * (128 * 128) + gc * 32;   // float4 units

    float s = 0.0f;
    #pragma unroll 8
    for (int i = 0; i < 64; i++) {
        const float4 v = p[cellbase + (r0 + 2 * i) * 128 + c4];
        s += (v.x + v.y) + (v.z + v.w);
    }

    #pragma unroll
    for (int o = 16; o > 0; o >>= 1)
        s += __shfl_xor_sync(0xffffffffu, s, o);

    __shared__ float ws[32];
    if ((t & 31) == 0) ws[t >> 5] = s;   // ws[w]: cell = w>>1, parity = w&1
    __syncthreads();

    if (t == 0) {
        float cells[16];
        #pragma unroll
        for (int i = 0; i < 16; i++) cells[i] = ws[2 * i] + ws[2 * i + 1];

        float best = -CUDART_INF_F;
        int   bi   = 0;
        #pragma unroll
        for (int r = 0; r < 2; r++) {
            #pragma unroll
            for (int c = 0; c < 2; c++) {
                float w = 0.0f;
                #pragma unroll
                for (int dr = 0; dr < 3; dr++)
                    #pragma unroll
                    for (int dc = 0; dc < 3; dc++)
                        w += cells[(r + dr) * 4 + (c + dc)];
                if (w > best) { best = w; bi = r * 2 + c; }
            }
        }
        // FLOAT output: row = idx/2, col = idx%2.
        out[b * 2 + 0] = (float)(bi >> 1);
        out[b * 2 + 1] = (float)(bi & 1);
    }
}

extern "C" void kernel_launch(void* const* d_in, const int* in_sizes, int n_in,
                              void* d_out, int out_size) {
    const float* x = (const float*)d_in[0];
    float* out = (float*)d_out;
    region_selector_kernel<<<128, 1024>>>(x, out);
}

// round 9
// speedup vs baseline: 1.0414x; 1.0414x over previous
#include <cuda_runtime.h>
#include <math_constants.h>

// One float per (batch, grid_row, grid_col): index == blockIdx.x of kernel 1.
__device__ float g_cells[128 * 4 * 4];

// ---------------------------------------------------------------------------
// Kernel 1: one block per grid cell. 2048 blocks x 256 threads.
// 256-thread blocks -> 8 blocks/SM (100% occ), all 148 SMs covered.
// Block bid: batch = bid>>4, cell = bid&15 (gr = cell>>2, gc = cell&3).
// Thread t: c4 = t&31 (float4 col within 128-float cell row), r0 = t>>5,
// rows r0 + 8i, i<16 -> 16 independent coalesced float4 loads (MLP 16).
// ---------------------------------------------------------------------------
__global__ __launch_bounds__(256) void cell_reduce_kernel(const float* __restrict__ x) {
    const int bid   = blockIdx.x;      // batch*16 + gr*4 + gc
    const int batch = bid >> 4;
    const int cell  = bid & 15;
    const int gr    = cell >> 2;
    const int gc    = cell & 3;

    const int t  = threadIdx.x;        // 0..255
    const int c4 = t & 31;
    const int r0 = t >> 5;             // 0..7

    const float4* __restrict__ p =
        reinterpret_cast<const float4*>(x) + (size_t)batch * 65536;
    const int cellbase = gr * (128 * 128) + gc * 32;   // float4 units

    float s = 0.0f;
    #pragma unroll
    for (int i = 0; i < 16; i++) {
        const float4 v = p[cellbase + (r0 + 8 * i) * 128 + c4];
        s += (v.x + v.y) + (v.z + v.w);
    }

    // Warp reduce, then combine 8 warp partials.
    #pragma unroll
    for (int o = 16; o > 0; o >>= 1)
        s += __shfl_xor_sync(0xffffffffu, s, o);

    __shared__ float ws[8];
    if ((t & 31) == 0) ws[t >> 5] = s;
    __syncthreads();

    if (t == 0) {
        float tot = (ws[0] + ws[1]) + (ws[2] + ws[3])
                  + (ws[4] + ws[5]) + (ws[6] + ws[7]);
        g_cells[bid] = tot;            // scratch index == block index
    }
}

// ---------------------------------------------------------------------------
// Kernel 2: one thread per batch. 16 cell sums -> four 3x3 window sums ->
// first-occurrence argmax -> float (row, col). /16384 mean scale skipped
// (uniform positive factor, argmax-invariant).
// ---------------------------------------------------------------------------
__global__ __launch_bounds__(128) void select_kernel(float* __restrict__ out) {
    const int b = threadIdx.x;
    if (b >= 128) return;

    float cells[16];
    #pragma unroll
    for (int i = 0; i < 16; i++) cells[i] = g_cells[b * 16 + i];

    float best = -CUDART_INF_F;
    int   bi   = 0;
    #pragma unroll
    for (int r = 0; r < 2; r++) {
        #pragma unroll
        for (int c = 0; c < 2; c++) {
            float w = 0.0f;
            #pragma unroll
            for (int dr = 0; dr < 3; dr++)
                #pragma unroll
                for (int dc = 0; dc < 3; dc++)
                    w += cells[(r + dr) * 4 + (c + dc)];
            if (w > best) { best = w; bi = r * 2 + c; }  // strict > = first hit
        }
    }
    out[b * 2 + 0] = (float)(bi >> 1);   // row
    out[b * 2 + 1] = (float)(bi & 1);    // col
}

extern "C" void kernel_launch(void* const* d_in, const int* in_sizes, int n_in,
                              void* d_out, int out_size) {
    const float* x = (const float*)d_in[0];
    float* out = (float*)d_out;

    cell_reduce_kernel<<<2048, 256>>>(x);
    select_kernel<<<1, 128>>>(out);
}